// round 13
// baseline (speedup 1.0000x reference)
#include <cuda_runtime.h>
#include <cuda_bf16.h>
#include <cstdint>

// Problem constants (fixed by the reference)
#define BB 256
#define TT 4096
#define FF 16
#define HH 64
#define NROWS (256*4096)   // 1048576 rows of (b,t)

// -------------------- scratch (device globals; no allocs allowed) -----------
// 4-wide interleaved xi layout: g_xi4[row][j][slot], slot: 0=ir,1=iz,2=inn,
// 3=xp (layer1) / garbage (layer2).  1.07 GB.
__device__ float g_xi4[(size_t)NROWS * 256];
__device__ float g_aux[(size_t)NROWS * 64];   // o2 (output of GRU2)
__device__ float g_o1 [(size_t)NROWS * 64];   // o1adj

// -------------------- packed f32x2 helpers ----------------------------------
__device__ __forceinline__ unsigned long long pk2(float lo, float hi) {
    unsigned long long d;
    asm("mov.b64 %0, {%1, %2};" : "=l"(d) : "f"(lo), "f"(hi));
    return d;
}
__device__ __forceinline__ void unpk2(unsigned long long v, float& lo, float& hi) {
    asm("mov.b64 {%0, %1}, %2;" : "=f"(lo), "=f"(hi) : "l"(v));
}
__device__ __forceinline__ unsigned long long ffma2(unsigned long long a,
                                                    unsigned long long b,
                                                    unsigned long long c) {
    unsigned long long d;
    asm("fma.rn.f32x2 %0, %1, %2, %3;" : "=l"(d) : "l"(a), "l"(b), "l"(c));
    return d;
}
__device__ __forceinline__ unsigned long long fadd2(unsigned long long a,
                                                    unsigned long long b) {
    unsigned long long d;
    asm("add.rn.f32x2 %0, %1, %2;" : "=l"(d) : "l"(a), "l"(b));
    return d;
}

// HW tanh (MUFU.TANH): ~6e-4 max abs error.
__device__ __forceinline__ float tanh_mufu(float x) {
    float y;
    asm("tanh.approx.f32 %0, %1;" : "=f"(y) : "f"(x));
    return y;
}

__device__ __forceinline__ uint32_t f2tf32(float f) {
    uint32_t u;
    asm("cvt.rna.tf32.f32 %0, %1;" : "=r"(u) : "f"(f));
    return u;
}

// ============================================================================
// proj1: xi1 = x@Wi1 + bi1 (192 cols), xp = x@Wp + bp (64 cols), written
// into the 4-wide layout via a shared-memory staging buffer (dense STG.128).
// ============================================================================
__global__ __launch_bounds__(256) void proj1_kernel(
    const float* __restrict__ X,
    const float* __restrict__ Wi1, const float* __restrict__ bi1,
    const float* __restrict__ Wp,  const float* __restrict__ bp)
{
    __shared__ __align__(16) unsigned long long xdup[8][16];  // 8 rows x 16 dup-pairs
    __shared__ __align__(16) float srow[8][256];              // staged 4-wide rows

    const int tid = threadIdx.x;
    const int j2  = tid & 127;   // output pair index
    const int rr  = tid >> 7;    // 0..1

    unsigned long long wp_[16];
    unsigned long long bias;
    int p0, p1;                  // destination slots within the 256-wide row
    if (j2 < 96) {               // xi columns c0, c0+1
        const int c0 = 2 * j2;
        const int g = c0 >> 6, j = c0 & 63;
        p0 = 4 * j + g; p1 = 4 * (j + 1) + g;
#pragma unroll
        for (int k = 0; k < 16; k++)
            wp_[k] = pk2(Wi1[k * 192 + c0], Wi1[k * 192 + c0 + 1]);
        bias = pk2(bi1[c0], bi1[c0 + 1]);
    } else {                     // xp columns c0, c0+1 -> slot 3
        const int c0 = 2 * j2 - 192;
        p0 = 4 * c0 + 3; p1 = 4 * (c0 + 1) + 3;
#pragma unroll
        for (int k = 0; k < 16; k++)
            wp_[k] = pk2(Wp[k * 64 + c0], Wp[k * 64 + c0 + 1]);
        bias = pk2(bp[c0], bp[c0 + 1]);
    }

    for (size_t r0 = (size_t)blockIdx.x * 8; r0 < (size_t)NROWS;
         r0 += (size_t)gridDim.x * 8) {
        if (tid < 32) {
            const float4* xs = (const float4*)(X + r0 * 16);
            float4 v = xs[tid];
            int row = tid >> 2, c4 = (tid & 3) * 4;
            xdup[row][c4 + 0] = pk2(v.x, v.x);
            xdup[row][c4 + 1] = pk2(v.y, v.y);
            xdup[row][c4 + 2] = pk2(v.z, v.z);
            xdup[row][c4 + 3] = pk2(v.w, v.w);
        }
        __syncthreads();
#pragma unroll
        for (int q = 0; q < 4; q++) {
            const int rw = rr * 4 + q;
            const ulonglong2* xr = (const ulonglong2*)&xdup[rw][0];
            unsigned long long acc = bias;
#pragma unroll
            for (int i = 0; i < 8; i++) {
                ulonglong2 u = xr[i];
                acc = ffma2(u.x, wp_[2 * i], acc);
                acc = ffma2(u.y, wp_[2 * i + 1], acc);
            }
            float lo, hi; unpk2(acc, lo, hi);
            srow[rw][p0] = lo;
            srow[rw][p1] = hi;
        }
        __syncthreads();
        // dense store: 8 rows x 64 float4
#pragma unroll
        for (int k = 0; k < 2; k++) {
            int f = tid + k * 256;
            int row = f >> 6, c4 = (f & 63) * 4;
            *(float4*)(g_xi4 + (r0 + row) * 256 + c4) = *(const float4*)&srow[row][c4];
        }
        __syncthreads();
    }
}

// ============================================================================
// proj2 via tf32 tensor-core mma with a 256-column PERMUTED B so that the
// output columns land dense in the 4-wide layout: B column p holds Wi2 column
// (p&3)*64 + (p>>2) for p&3<3, zeros for slot-3 columns (stored, never read).
// CTA = 256 threads (8 warps): warps 0-3 rows [16w,16w+16) x cols [0,128),
// warps 4-7 same rows x cols [128,256). K=64 -> 8 mma k-steps. Dynamic smem.
// ============================================================================
__global__ __launch_bounds__(256) void proj2_mma_kernel(
    const float* __restrict__ Wi2, const float* __restrict__ bi2)
{
    extern __shared__ uint32_t dynsmem[];
    uint32_t (*As)[68]  = (uint32_t(*)[68])dynsmem;            // 64x68  (17408 B)
    uint32_t (*Bs)[264] = (uint32_t(*)[264])(dynsmem + 64*68); // 64x264 (67584 B)

    const int tid  = threadIdx.x;
    const int warp = tid >> 5, lane = tid & 31;
    const int g    = lane >> 2, tig = lane & 3;
    const int rw   = 16 * (warp & 3);
    const int ntb  = (warp >> 2) * 16;

    // Load permuted B: Bs[k][p] = tf32(Wi2[k][ (p&3)*64 + (p>>2) ]) or 0
    for (int f = tid; f < 64 * 256; f += 256) {
        int k = f >> 8, p = f & 255;
        int slot = p & 3, j = p >> 2;
        float v = (slot < 3) ? Wi2[k * 192 + slot * 64 + j] : 0.f;
        Bs[k][p] = f2tf32(v);
    }

    // Per-thread bias pairs (col pair c0,c0+1 per nt)
    float bx[16], by[16];
#pragma unroll
    for (int nt = 0; nt < 16; nt++) {
        int c0 = (ntb + nt) * 8 + 2 * tig;
        int j = c0 >> 2;
        bx[nt] = bi2[(c0 & 3) * 64 + j];
        by[nt] = (((c0 + 1) & 3) == 3) ? 0.f : bi2[((c0 + 1) & 3) * 64 + j];
    }

    for (size_t r0 = (size_t)blockIdx.x * 64; r0 < (size_t)NROWS;
         r0 += (size_t)gridDim.x * 64) {
        __syncthreads();   // B ready (iter 0) / prev mma reads of As done
        // Stage A tile 64x64 -> tf32 shared
        for (int f = tid; f < 64 * 16; f += 256) {
            int row = f >> 4, c4 = (f & 15) * 4;
            float4 v = *(const float4*)(g_o1 + (r0 + row) * 64 + c4);
            As[row][c4 + 0] = f2tf32(v.x);
            As[row][c4 + 1] = f2tf32(v.y);
            As[row][c4 + 2] = f2tf32(v.z);
            As[row][c4 + 3] = f2tf32(v.w);
        }
        __syncthreads();

        float acc[16][4];
#pragma unroll
        for (int nt = 0; nt < 16; nt++)
            acc[nt][0] = acc[nt][1] = acc[nt][2] = acc[nt][3] = 0.f;

#pragma unroll
        for (int ks = 0; ks < 8; ks++) {
            const int k0 = ks * 8;
            uint32_t a0 = As[rw + g    ][k0 + tig];
            uint32_t a1 = As[rw + g + 8][k0 + tig];
            uint32_t a2 = As[rw + g    ][k0 + tig + 4];
            uint32_t a3 = As[rw + g + 8][k0 + tig + 4];
#pragma unroll
            for (int nt = 0; nt < 16; nt++) {
                uint32_t b0 = Bs[k0 + tig    ][(ntb + nt) * 8 + g];
                uint32_t b1 = Bs[k0 + tig + 4][(ntb + nt) * 8 + g];
                asm("mma.sync.aligned.m16n8k8.row.col.f32.tf32.tf32.f32 "
                    "{%0,%1,%2,%3}, {%4,%5,%6,%7}, {%8,%9}, {%0,%1,%2,%3};"
                    : "+f"(acc[nt][0]), "+f"(acc[nt][1]),
                      "+f"(acc[nt][2]), "+f"(acc[nt][3])
                    : "r"(a0), "r"(a1), "r"(a2), "r"(a3), "r"(b0), "r"(b1));
            }
        }

        // Epilogue: dense float2 stores into the 4-wide layout
        const size_t row = r0 + rw + g;
#pragma unroll
        for (int nt = 0; nt < 16; nt++) {
            const int c0 = (ntb + nt) * 8 + 2 * tig;
            float2 o0 = make_float2(acc[nt][0] + bx[nt], acc[nt][1] + by[nt]);
            float2 o1v = make_float2(acc[nt][2] + bx[nt], acc[nt][3] + by[nt]);
            *(float2*)(g_xi4 + row * 256 + c0) = o0;
            *(float2*)(g_xi4 + (row + 8) * 256 + c0) = o1v;
        }
    }
}

// ============================================================================
// GRU recurrence — R10.
// One CTA per batch row, 128 threads = 64 columns x 2 k-halves.
// Changes vs R7:
//  - ONE LDG.128 per thread per step (4-wide xi layout) instead of 3-4 LDG.32
//  - 0.5*ir / 0.5*iz folded into dot-accumulator init (off critical path);
//    bhn/2 folded into a precomputed init pack -> post-shfl path is
//    tanh -> fma -> tanh -> fma only
// ============================================================================
__global__ __launch_bounds__(128, 2) void gru_kernel(
    const float* __restrict__ Whr, const float* __restrict__ Whz,
    const float* __restrict__ Whn, const float* __restrict__ bhn,
    int layer2)
{
    const int tid = threadIdx.x;
    const int j   = tid >> 1;     // 0..63 output column
    const int s   = tid & 1;      // k-half
    const int b   = blockIdx.x;
    const int k0  = 32 * s;

    float* out = layer2 ? g_aux : g_o1;

    __shared__ __align__(16) float hbuf[2][72];  // halves at [0,32) and [36,68)

    unsigned long long wr_[16], wz_[16], wn_[16];
#pragma unroll
    for (int i = 0; i < 16; i++) {
        // r/z kernels pre-scaled by 0.5 (sigmoid-via-tanh folding)
        wr_[i] = pk2(0.5f * Whr[(k0 + 2 * i) * 64 + j],
                     0.5f * Whr[(k0 + 2 * i + 1) * 64 + j]);
        wz_[i] = pk2(0.5f * Whz[(k0 + 2 * i) * 64 + j],
                     0.5f * Whz[(k0 + 2 * i + 1) * 64 + j]);
        wn_[i] = pk2(Whn[(k0 + 2 * i) * 64 + j],
                     Whn[(k0 + 2 * i + 1) * 64 + j]);
    }
    // each half contributes bn/2 -> total bn folded into the n-dot
    const unsigned long long bnq = pk2(0.5f * bhn[j], 0.f);
    const int jpad = j + ((j >> 5) << 2);   // j<32 -> j ; j>=32 -> j+4

    if (tid < 72) hbuf[0][tid] = 0.0f;      // h0 = 0 (covers both halves+pad)

    const float4* pv = (const float4*)(g_xi4 + (size_t)b * TT * 256) + j;
    const float*  pa = g_o1 + (size_t)b * TT * 64 + j;   // aux (layer2 only)
    float*        op = out + (size_t)b * TT * 64 + j;

    // 4-deep register prefetch queues (slot u refilled with step tb+u+4)
    float4 qv[4];
    float  qa[4] = {0.f, 0.f, 0.f, 0.f};
#pragma unroll
    for (int u = 0; u < 4; u++) {
        qv[u] = __ldg(pv + (size_t)u * 64);
        if (layer2 && s) qa[u] = __ldg(pa + u * 64);
    }
    pv += 4 * 64; pa += 4 * 64;

    float hprev = 0.0f;
    __syncthreads();

    int buf = 0;
    for (int tb = 0; tb < TT; tb += 4) {
        const bool pf = (tb + 4) < TT;
#pragma unroll
        for (int u = 0; u < 4; u++) {
            const float4 v = qv[u];
            const float inn = v.z;
            const float av  = layer2 ? qa[u] : v.w;

            // accumulator inits fold 0.5*ix (per half -> 0.25*ix each) and bn/2
            unsigned long long r0 = pk2(0.25f * v.x, 0.f), r1 = 0ull;
            unsigned long long z0 = pk2(0.25f * v.y, 0.f), z1 = 0ull;
            unsigned long long n0 = bnq,                   n1 = 0ull;

            // ---- critical LDS + partial dots (no LDGs ahead of them)
            const ulonglong2* hp = (const ulonglong2*)&hbuf[buf][36 * s];
#pragma unroll
            for (int i = 0; i < 8; i++) {
                ulonglong2 h2 = hp[i];
                r0 = ffma2(h2.x, wr_[2 * i],     r0);
                r1 = ffma2(h2.y, wr_[2 * i + 1], r1);
                z0 = ffma2(h2.x, wz_[2 * i],     z0);
                z1 = ffma2(h2.y, wz_[2 * i + 1], z1);
                n0 = ffma2(h2.x, wn_[2 * i],     n0);
                n1 = ffma2(h2.y, wn_[2 * i + 1], n1);
            }

            // ---- prefetch t+4 now (fills the gate-tail latency shadow)
            if (pf) {
                qv[u] = __ldg(pv);
                if (layer2 && s) qa[u] = __ldg(pa);
            }
            pv += 64; pa += 64;

            float lo, hi;
            r0 = fadd2(r0, r1); unpk2(r0, lo, hi); float dr = lo + hi;
            z0 = fadd2(z0, z1); unpk2(z0, lo, hi); float dz = lo + hi;
            n0 = fadd2(n0, n1); unpk2(n0, lo, hi); float dn = lo + hi;
            dr += __shfl_xor_sync(0xffffffffu, dr, 1);  // = 0.5*(ir + dot_r)
            dz += __shfl_xor_sync(0xffffffffu, dz, 1);  // = 0.5*(iz + dot_z)
            dn += __shfl_xor_sync(0xffffffffu, dn, 1);  // = dot_n + bn

            const float rg = fmaf(0.5f, tanh_mufu(dr), 0.5f);
            const float zg = fmaf(0.5f, tanh_mufu(dz), 0.5f);
            const float n  = tanh_mufu(fmaf(rg, dn, inn));
            const float hn = n + zg * (hprev - n);
            hprev = hn;
            if (s) *op = hn + 0.5f * av;          // s=1: write output
            else   hbuf[buf ^ 1][jpad] = hn;      // s=0: publish h for t+1
            op += 64;
            __syncthreads();                      // single barrier per step
            buf ^= 1;
        }
    }
}

// ============================================================================
// Attention + MLP head, single HBM pass: 256-row tiles; scores+exp in phase A
// (tile stays L1-resident), weighted accumulation re-reads it from L1 in
// phase B. No max subtraction (scores ~N(0,1.3); exp safe in fp32).
// ============================================================================
__global__ __launch_bounds__(256) void att_mlp_kernel(
    const float* __restrict__ Wa, const float* __restrict__ ba,
    const float* __restrict__ W1, const float* __restrict__ b1,
    const float* __restrict__ W2, const float* __restrict__ b2,
    const float* __restrict__ W3, const float* __restrict__ b3,
    const float* __restrict__ W4, const float* __restrict__ b4,
    float* __restrict__ outp)
{
    const int b = blockIdx.x, tid = threadIdx.x;
    __shared__ float sc[256];
    __shared__ float red[256];
    __shared__ float wash[64];
    __shared__ float att[64];
    __shared__ float h1s[128];
    __shared__ float h2s[64];
    __shared__ float h3s[32];

    if (tid < 64) wash[tid] = Wa[tid];
    __syncthreads();

    const float* o2b = g_aux + (size_t)b * TT * 64;
    const int jj = tid & 63, ch = tid >> 6;

    float lsum = 0.f;
    float attp = 0.f;   // partial attended[jj] over this thread's t-subset

    for (int tile = 0; tile < TT / 256; tile++) {
        // phase A: score + exp for row t = tile*256 + tid
        {
            const int t = tile * 256 + tid;
            const float4* rowp = (const float4*)(o2b + (size_t)t * 64);
            float s = 0.f;
#pragma unroll
            for (int i = 0; i < 16; i++) {
                float4 v = rowp[i];
                s += v.x * wash[4 * i] + v.y * wash[4 * i + 1]
                   + v.z * wash[4 * i + 2] + v.w * wash[4 * i + 3];
            }
            float e = __expf(s + ba[0]);
            sc[tid] = e;
            lsum += e;
        }
        __syncthreads();
        // phase B: thread (jj,ch) accumulates over 64 tile rows (L1 hits)
        {
            const int t0 = tile * 256 + ch * 64;
            const float* base = o2b + (size_t)t0 * 64 + jj;
            const float* e = &sc[ch * 64];
            float c0 = 0.f, c1 = 0.f, c2 = 0.f, c3 = 0.f;
#pragma unroll 4
            for (int i = 0; i < 64; i += 4) {
                c0 += e[i + 0] * base[(i + 0) * 64];
                c1 += e[i + 1] * base[(i + 1) * 64];
                c2 += e[i + 2] * base[(i + 2) * 64];
                c3 += e[i + 3] * base[(i + 3) * 64];
            }
            attp += (c0 + c1) + (c2 + c3);
        }
        __syncthreads();
    }

    // reduce expsum
    red[tid] = lsum; __syncthreads();
    for (int off = 128; off > 0; off >>= 1) {
        if (tid < off) red[tid] += red[tid + off];
        __syncthreads();
    }
    const float inv = __fdividef(1.0f, red[0]);
    __syncthreads();

    // reduce attended
    red[tid] = attp; __syncthreads();
    if (tid < 64)
        att[tid] = (red[tid] + red[tid + 64] + red[tid + 128] + red[tid + 192]) * inv;
    __syncthreads();

    // MLP head
    if (tid < 128) {
        float s = b1[tid];
#pragma unroll
        for (int k = 0; k < 64; k++) s += att[k] * W1[k * 128 + tid];
        h1s[tid] = fmaxf(s, 0.f);
    }
    __syncthreads();
    if (tid < 64) {
        float s = b2[tid];
#pragma unroll
        for (int k = 0; k < 128; k++) s += h1s[k] * W2[k * 64 + tid];
        h2s[tid] = fmaxf(s, 0.f);
    }
    __syncthreads();
    if (tid < 32) {
        float s = b3[tid];
#pragma unroll
        for (int k = 0; k < 64; k++) s += h2s[k] * W3[k * 32 + tid];
        h3s[tid] = fmaxf(s, 0.f);
    }
    __syncthreads();
    if (tid < 2) {
        float s = b4[tid];
#pragma unroll
        for (int k = 0; k < 32; k++) s += h3s[k] * W4[k * 2 + tid];
        outp[b * 2 + tid] = s;
    }
}

// ============================================================================
extern "C" void kernel_launch(void* const* d_in, const int* in_sizes, int n_in,
                              void* d_out, int out_size)
{
    const float* x    = (const float*)d_in[0];
    const float* Wi1  = (const float*)d_in[1];
    const float* bi1  = (const float*)d_in[2];
    const float* Whr1 = (const float*)d_in[3];
    const float* Whz1 = (const float*)d_in[4];
    const float* Whn1 = (const float*)d_in[5];
    const float* bhn1 = (const float*)d_in[6];
    const float* Wi2  = (const float*)d_in[7];
    const float* bi2  = (const float*)d_in[8];
    const float* Whr2 = (const float*)d_in[9];
    const float* Whz2 = (const float*)d_in[10];
    const float* Whn2 = (const float*)d_in[11];
    const float* bhn2 = (const float*)d_in[12];
    const float* Wp   = (const float*)d_in[13];
    const float* bp   = (const float*)d_in[14];
    const float* Wa   = (const float*)d_in[15];
    const float* ba   = (const float*)d_in[16];
    const float* W1   = (const float*)d_in[17];
    const float* b1   = (const float*)d_in[18];
    const float* W2   = (const float*)d_in[19];
    const float* b2   = (const float*)d_in[20];
    const float* W3   = (const float*)d_in[21];
    const float* b3   = (const float*)d_in[22];
    const float* W4   = (const float*)d_in[23];
    const float* b4   = (const float*)d_in[24];
    float* outp = (float*)d_out;

    const int proj2_smem = (64 * 68 + 64 * 264) * 4;  // 84992 B
    cudaFuncSetAttribute(proj2_mma_kernel,
                         cudaFuncAttributeMaxDynamicSharedMemorySize, proj2_smem);

    // 1. xi1 = x@Wi1+bi1, xp = x@Wp+bp -> g_xi4 (4-wide interleaved)
    proj1_kernel<<<592, 256>>>(x, Wi1, bi1, Wp, bp);
    // 2. GRU layer 1 -> g_o1 = gru(x) + 0.5*xp
    gru_kernel<<<256, 128>>>(Whr1, Whz1, Whn1, bhn1, 0);
    // 3. xi2 = o1adj@Wi2+bi2 -> g_xi4 (tf32 mma, permuted-B dense stores)
    proj2_mma_kernel<<<296, 256, proj2_smem>>>(Wi2, bi2);
    // 4. GRU layer 2 -> g_aux = gru(o1adj) + 0.5*o1adj  (= o2)
    gru_kernel<<<256, 128>>>(Whr2, Whz2, Whn2, bhn2, 1);
    // 5. attention softmax + MLP head -> out (B,2)
    att_mlp_kernel<<<BB, 256>>>(Wa, ba, W1, b1, W2, b2, W3, b3, W4, b4, outp);
}